// round 16
// baseline (speedup 1.0000x reference)
#include <cuda_runtime.h>
#include <cuda_fp16.h>
#include <math.h>
#include <cstdint>

#define TOTE (4096 * 768)
#define WELE (768 * 768)
#define AST 72     // fp16 smem row stride for 64-wide tiles (144B)
#define WSTW 36    // W fp32 smem row stride (144B)

// Scratch (allocation-free rule: __device__ globals)
__device__ __half g_qf16[TOTE];        // query fp16
__device__ __half g_wf16[4 * WELE];    // Wq|Wk|Wv|Wo fp16
__device__ __half g_qk16[2 * TOTE];    // Q|K fp16
__device__ __half g_vf[TOTE];          // V fp16
__device__ __half g_att16[TOTE];       // attention output fp16

// ===========================================================================
// Base-sm_103-safe helpers (no tcgen05: ptxas virtual target is compute_103)
// ===========================================================================
__device__ __forceinline__ uint32_t smem_u32(const void* p) {
    uint32_t a;
    asm("{ .reg .u64 t; cvta.to.shared.u64 t, %1; cvt.u32.u64 %0, t; }" : "=r"(a) : "l"(p));
    return a;
}
__device__ __forceinline__ void ldsm_x4(uint32_t* r, uint32_t addr) {
    asm volatile("ldmatrix.sync.aligned.m8n8.x4.shared.b16 {%0,%1,%2,%3}, [%4];"
                 : "=r"(r[0]), "=r"(r[1]), "=r"(r[2]), "=r"(r[3]) : "r"(addr));
}
__device__ __forceinline__ void ldsm_x4_t(uint32_t* r, uint32_t addr) {
    asm volatile("ldmatrix.sync.aligned.m8n8.x4.trans.shared.b16 {%0,%1,%2,%3}, [%4];"
                 : "=r"(r[0]), "=r"(r[1]), "=r"(r[2]), "=r"(r[3]) : "r"(addr));
}
__device__ __forceinline__ void mma_f16(float* d, const uint32_t* a, uint32_t b0, uint32_t b1) {
    asm volatile(
        "mma.sync.aligned.m16n8k16.row.col.f32.f16.f16.f32 "
        "{%0,%1,%2,%3}, {%4,%5,%6,%7}, {%8,%9}, {%0,%1,%2,%3};"
        : "+f"(d[0]), "+f"(d[1]), "+f"(d[2]), "+f"(d[3])
        : "r"(a[0]), "r"(a[1]), "r"(a[2]), "r"(a[3]), "r"(b0), "r"(b1));
}
__device__ __forceinline__ uint32_t pack_f16x2(float lo, float hi) {
    uint32_t d;
    asm("cvt.rn.f16x2.f32 %0, %1, %2;" : "=r"(d) : "f"(hi), "f"(lo));
    return d;
}
__device__ __forceinline__ void cpa16(uint32_t dst, const void* src) {
    asm volatile("cp.async.cg.shared.global [%0], [%1], 16;" :: "r"(dst), "l"(src) : "memory");
}
#define CPW(n) asm volatile("cp.async.wait_group " #n ";" ::: "memory")

// ===========================================================================
// Fused conversion: query + all four weights -> fp16, one launch.
// ===========================================================================
__global__ __launch_bounds__(256) void conv_all(
    const float4* __restrict__ q,
    const float4* __restrict__ Wq, const float4* __restrict__ Wk,
    const float4* __restrict__ Wv, const float4* __restrict__ Wo,
    uint2* __restrict__ qf16, uint2* __restrict__ wf16)
{
    const int bid = blockIdx.x;
    const int tid = threadIdx.x;
    if (bid < 3072) {
        int i = bid * 256 + tid;
        float4 v = q[i];
        __half f[4] = {__float2half_rn(v.x), __float2half_rn(v.y),
                       __float2half_rn(v.z), __float2half_rn(v.w)};
        qf16[i] = *(uint2*)f;
    } else {
        int r = bid - 3072;
        int zz = r / 576;
        int i = (r % 576) * 256 + tid;
        const float4* src = (zz == 0) ? Wq : (zz == 1) ? Wk : (zz == 2) ? Wv : Wo;
        float4 v = src[i];
        __half f[4] = {__float2half_rn(v.x), __float2half_rn(v.y),
                       __float2half_rn(v.z), __float2half_rn(v.w)};
        wf16[(size_t)zz * (WELE / 4) + i] = *(uint2*)f;
    }
}

// ===========================================================================
// Q/K/V projections: single-pass fp16 NT GEMM, one launch (z selects weight
// + output). Block tile 128x128, K-chunk 64, 3-stage cp.async, 2 CTAs/SM.
// ===========================================================================
#define FTA (128 * AST * 2)          // bytes per array per stage (18432)
#define FSTB (2 * FTA)               // stage stride (36864)

__global__ __launch_bounds__(256, 2) void proj_qkv(
    const __half* __restrict__ Af, const __half* __restrict__ Wf,
    __half* __restrict__ qk, __half* __restrict__ vf)
{
    extern __shared__ __align__(16) __half smh[];
    const uint32_t sb = smem_u32(smh);

    const int tid = threadIdx.x, wid = tid >> 5, lane = tid & 31;
    const int wm = (wid >> 1) * 32, wn = (wid & 1) * 64;
    const int m0 = blockIdx.y * 128, n0 = blockIdx.x * 128;
    const int z = blockIdx.z;

    const __half* gA = Af + (size_t)m0 * 768;
    const __half* gB = Wf + (size_t)z * WELE + (size_t)n0 * 768;
    __half* dst = (z == 2) ? vf : qk + (size_t)z * TOTE;

    float acc[2][8][4];
#pragma unroll
    for (int i = 0; i < 2; i++)
#pragma unroll
        for (int j = 0; j < 8; j++)
#pragma unroll
            for (int k = 0; k < 4; k++) acc[i][j][k] = 0.f;

#define PSTAGE(buf, c_)                                                        \
    {                                                                          \
        uint32_t base_ = sb + (buf) * FSTB;                                    \
        const int k0_ = (c_) * 64;                                             \
        _Pragma("unroll")                                                      \
        for (int it = 0; it < 4; it++) {                                       \
            int idx = it * 256 + tid;                                          \
            int row = idx >> 3, cc = idx & 7;                                  \
            uint32_t off = (uint32_t)(row * AST + cc * 8) * 2;                 \
            size_t go = (size_t)row * 768 + k0_ + cc * 8;                      \
            cpa16(base_ + off,       gA + go);                                 \
            cpa16(base_ + FTA + off, gB + go);                                 \
        }                                                                      \
        asm volatile("cp.async.commit_group;" ::: "memory");                   \
    }

    PSTAGE(0, 0); PSTAGE(1, 1);

    const int lrow = lane & 15, lcol8 = (lane >> 4) * 8;
    const uint32_t offA = (uint32_t)((wm + lrow) * AST + lcol8) * 2;
    const uint32_t offB = (uint32_t)((wn + lrow) * AST + lcol8) * 2;

    for (int c = 0; c < 12; c++) {
        if (c + 2 < 12) { CPW(1); } else { CPW(0); }
        __syncthreads();
        if (c + 2 < 12) PSTAGE((c + 2) % 3, c + 2);
        uint32_t base = sb + (c % 3) * FSTB;
        uint32_t aA = base + offA, aB = base + FTA + offB;
#pragma unroll
        for (int kk = 0; kk < 4; kk++) {
            const uint32_t koff = kk * 32;
            uint32_t af[2][4];
#pragma unroll
            for (int mf = 0; mf < 2; mf++)
                ldsm_x4(af[mf], aA + mf * 16 * AST * 2 + koff);
#pragma unroll
            for (int nq = 0; nq < 4; nq++) {
                uint32_t bq[4];
                ldsm_x4(bq, aB + nq * 16 * AST * 2 + koff);
#pragma unroll
                for (int mf = 0; mf < 2; mf++) {
                    mma_f16(acc[mf][nq * 2 + 0], af[mf], bq[0], bq[2]);
                    mma_f16(acc[mf][nq * 2 + 1], af[mf], bq[1], bq[3]);
                }
            }
        }
    }

#pragma unroll
    for (int mf = 0; mf < 2; mf++) {
#pragma unroll
        for (int nf = 0; nf < 8; nf++) {
            int row = m0 + wm + mf * 16 + (lane >> 2);
            int col = n0 + wn + nf * 8 + (lane & 3) * 2;
            __half2 h0 = __floats2half2_rn(acc[mf][nf][0], acc[mf][nf][1]);
            __half2 h1 = __floats2half2_rn(acc[mf][nf][2], acc[mf][nf][3]);
            *(uint32_t*)(dst + (size_t)row * 768 + col) = *(uint32_t*)&h0;
            *(uint32_t*)(dst + (size_t)(row + 8) * 768 + col) = *(uint32_t*)&h1;
        }
    }
}

// ===========================================================================
// HMMA fused biased flash attention: fp16 QK + fp16 PV, no-max softmax.
// Key tile 32, 4-stage cp.async (K + V + W, 3 stages in flight), 2 CTAs/SM.
// ===========================================================================
#define KT 32
#define KVB (KT * AST * 2)            // 4608 B per K/V array per stage
#define WB  (128 * WSTW * 4)          // 18432 B W tile per stage
#define STB (2 * KVB + WB)            // stage stride 27648 B

__global__ __launch_bounds__(256, 2) void attn_mma(
    const __half* __restrict__ qk16, const __half* __restrict__ vf,
    const float* __restrict__ W, __half* __restrict__ att16)
{
    extern __shared__ __align__(16) char smn[];
    const uint32_t sb = smem_u32(smn);

    const int tid = threadIdx.x, wp = tid >> 5, lane = tid & 31;
    const int n0 = blockIdx.x * 128, h = blockIdx.y, b = blockIdx.z;

    const __half* qg = qk16 + ((size_t)(b * 1024 + n0)) * 768 + h * 64;
    const __half* kg = qk16 + (size_t)TOTE + (size_t)b * 1024 * 768 + h * 64;
    const __half* vg = vf + (size_t)b * 1024 * 768 + h * 64;
    const float* wg = W + ((size_t)(b * 12 + h) * 1024 + n0) * 1024;

    // --- Stage Q (128x64 fp16) through smem (pre-pipeline), frags to regs ---
    {
        __half* tQ = (__half*)smn;
#pragma unroll
        for (int it = 0; it < 4; it++) {
            int idx = it * 256 + tid;
            int row = idx >> 3, cc = idx & 7;
            *(uint4*)(tQ + row * AST + cc * 8) = *(const uint4*)(qg + (size_t)row * 768 + cc * 8);
        }
    }
    __syncthreads();
    uint32_t qf[4][4];
    {
        uint32_t off = (uint32_t)((wp * 16 + (lane & 15)) * AST + (lane >> 4) * 8) * 2;
#pragma unroll
        for (int ks = 0; ks < 4; ks++)
            ldsm_x4(qf[ks], sb + off + ks * 32);
    }
    __syncthreads();

    float oacc[8][4];
#pragma unroll
    for (int d = 0; d < 8; d++)
#pragma unroll
        for (int j = 0; j < 4; j++) oacc[d][j] = 0.f;
    float l0r = 0.f, l1r = 0.f;

#define ASTAGE(buf, t_)                                                        \
    {                                                                          \
        uint32_t base_ = sb + (buf) * STB;                                     \
        const int s0_ = (t_) * KT;                                             \
        {                                                                      \
            int row = tid >> 3, cc = tid & 7;                                  \
            uint32_t doff = (uint32_t)(row * AST + cc * 8) * 2;                \
            size_t go = (size_t)(s0_ + row) * 768 + cc * 8;                    \
            cpa16(base_ + doff,       kg + go);                                \
            cpa16(base_ + KVB + doff, vg + go);                                \
        }                                                                      \
        _Pragma("unroll")                                                      \
        for (int it = 0; it < 4; it++) {                                       \
            int idx = it * 256 + tid;                                          \
            int row = idx >> 3, cc = idx & 7;                                  \
            cpa16(base_ + 2 * KVB + (uint32_t)(row * WSTW + cc * 4) * 4,       \
                  wg + (size_t)row * 1024 + s0_ + cc * 4);                     \
        }                                                                      \
        asm volatile("cp.async.commit_group;" ::: "memory");                   \
    }

    ASTAGE(0, 0); ASTAGE(1, 1); ASTAGE(2, 2);

    const uint32_t foff = (uint32_t)(((lane & 15) * AST) + (lane >> 4) * 8) * 2;
    const int c0 = (lane & 3) * 2;
    const uint32_t woff = (uint32_t)((wp * 16 + (lane >> 2)) * WSTW + c0) * 4;

    for (int t = 0; t < 32; t++) {
        {
            int rem = 31 - t;   // stages beyond t still needed
            if (rem >= 2) { CPW(2); } else if (rem == 1) { CPW(1); } else { CPW(0); }
        }
        __syncthreads();
        if (t + 3 < 32) ASTAGE((t + 3) & 3, t + 3);   // buf read at t-1: safe
        uint32_t base = sb + (t & 3) * STB;
        uint32_t kbb = base + foff;
        uint32_t vbb = base + KVB + foff;
        uint32_t wb0 = base + 2 * KVB + woff;

        // ---- S = Q K^T (fp16), 32 keys ----
        float sc[4][4];
#pragma unroll
        for (int nf = 0; nf < 4; nf++)
#pragma unroll
            for (int j = 0; j < 4; j++) sc[nf][j] = 0.f;
#pragma unroll
        for (int nf2 = 0; nf2 < 2; nf2++) {
#pragma unroll
            for (int ks = 0; ks < 4; ks++) {
                uint32_t fh[4];
                ldsm_x4(fh, kbb + (uint32_t)(nf2 * 16 * AST + ks * 16) * 2);
                mma_f16(sc[2 * nf2],     qf[ks], fh[0], fh[2]);
                mma_f16(sc[2 * nf2 + 1], qf[ks], fh[1], fh[3]);
            }
        }

        // ---- p = exp(W + scale*S) directly (bounded logits, no max) ----
        float rs0 = 0.f, rs1 = 0.f;
#pragma unroll
        for (int nf = 0; nf < 4; nf++) {
            float2 w0, w1;
            asm volatile("ld.shared.v2.f32 {%0,%1}, [%2];"
                         : "=f"(w0.x), "=f"(w0.y) : "r"(wb0 + nf * 32));
            asm volatile("ld.shared.v2.f32 {%0,%1}, [%2];"
                         : "=f"(w1.x), "=f"(w1.y) : "r"(wb0 + 8 * WSTW * 4 + nf * 32));
            sc[nf][0] = __expf(fmaf(sc[nf][0], 0.125f, w0.x));
            sc[nf][1] = __expf(fmaf(sc[nf][1], 0.125f, w0.y));
            sc[nf][2] = __expf(fmaf(sc[nf][2], 0.125f, w1.x));
            sc[nf][3] = __expf(fmaf(sc[nf][3], 0.125f, w1.y));
            rs0 += sc[nf][0] + sc[nf][1];
            rs1 += sc[nf][2] + sc[nf][3];
        }
        l0r += rs0;
        l1r += rs1;

        // ---- out += P V (fp16, P from registers) ----
#pragma unroll
        for (int kc = 0; kc < 2; kc++) {
            uint32_t pa[4];
            pa[0] = pack_f16x2(sc[2 * kc][0], sc[2 * kc][1]);
            pa[1] = pack_f16x2(sc[2 * kc][2], sc[2 * kc][3]);
            pa[2] = pack_f16x2(sc[2 * kc + 1][0], sc[2 * kc + 1][1]);
            pa[3] = pack_f16x2(sc[2 * kc + 1][2], sc[2 * kc + 1][3]);
#pragma unroll
            for (int dp = 0; dp < 4; dp++) {
                uint32_t vf4[4];
                ldsm_x4_t(vf4, vbb + (uint32_t)(kc * 16 * AST + dp * 16) * 2);
                mma_f16(oacc[2 * dp],     pa, vf4[0], vf4[1]);
                mma_f16(oacc[2 * dp + 1], pa, vf4[2], vf4[3]);
            }
        }
    }

    // ---- normalize + write fp16 (att layout [4096, 768]) ----
    l0r += __shfl_xor_sync(0xffffffffu, l0r, 1);
    l0r += __shfl_xor_sync(0xffffffffu, l0r, 2);
    l1r += __shfl_xor_sync(0xffffffffu, l1r, 1);
    l1r += __shfl_xor_sync(0xffffffffu, l1r, 2);
    float i0 = 1.f / l0r, i1 = 1.f / l1r;
    int row = b * 1024 + n0 + wp * 16 + (lane >> 2);
    int colb = h * 64 + c0;
#pragma unroll
    for (int d = 0; d < 8; d++) {
        __half2 h0 = __floats2half2_rn(oacc[d][0] * i0, oacc[d][1] * i0);
        __half2 h1 = __floats2half2_rn(oacc[d][2] * i1, oacc[d][3] * i1);
        *(uint32_t*)(att16 + (size_t)row * 768 + colb + d * 8) = *(uint32_t*)&h0;
        *(uint32_t*)(att16 + (size_t)(row + 8) * 768 + colb + d * 8) = *(uint32_t*)&h1;
    }
}

// ===========================================================================
// Output projection: single-pass fp16 NT GEMM, fp32 + bias epilogue.
// Block tile 64x64 (768 CTAs: fine-grained SM balance), K-chunk 64, 4-stage,
// 2 CTAs/SM. 8 warps = 4m x 2n, warp tile 16x32.
// ===========================================================================
#define OTC (64 * AST * 2)           // bytes per array per stage (9216)
#define OSTB (2 * OTC)               // stage stride (18432)

__global__ __launch_bounds__(256, 2) void gemm_out(
    const __half* __restrict__ Af, const __half* __restrict__ Bf,
    const float* __restrict__ bias, float* __restrict__ Cf)
{
    extern __shared__ __align__(16) __half smh[];
    const uint32_t sb = smem_u32(smh);

    const int tid = threadIdx.x, wid = tid >> 5, lane = tid & 31;
    const int wm = (wid >> 1) * 16, wn = (wid & 1) * 32;
    const int m0 = blockIdx.y * 64, n0 = blockIdx.x * 64;

    const __half* gA = Af + (size_t)m0 * 768;
    const __half* gB = Bf + (size_t)n0 * 768;

    float acc[4][4];
#pragma unroll
    for (int j = 0; j < 4; j++)
#pragma unroll
        for (int k = 0; k < 4; k++) acc[j][k] = 0.f;

#define OSTAGE(buf, c_)                                                        \
    {                                                                          \
        uint32_t base_ = sb + (buf) * OSTB;                                    \
        const int k0_ = (c_) * 64;                                             \
        _Pragma("unroll")                                                      \
        for (int it = 0; it < 2; it++) {                                       \
            int idx = it * 256 + tid;                                          \
            int row = idx >> 3, cc = idx & 7;                                  \
            uint32_t off = (uint32_t)(row * AST + cc * 8) * 2;                 \
            size_t go = (size_t)row * 768 + k0_ + cc * 8;                      \
            cpa16(base_ + off,       gA + go);                                 \
            cpa16(base_ + OTC + off, gB + go);                                 \
        }                                                                      \
        asm volatile("cp.async.commit_group;" ::: "memory");                   \
    }

    OSTAGE(0, 0); OSTAGE(1, 1); OSTAGE(2, 2);

    const int lrow = lane & 15, lcol8 = (lane >> 4) * 8;
    const uint32_t offA = (uint32_t)((wm + lrow) * AST + lcol8) * 2;
    const uint32_t offB = (uint32_t)((wn + lrow) * AST + lcol8) * 2;

    for (int c = 0; c < 12; c++) {
        {
            int rem = 11 - c;
            if (rem >= 2) { CPW(2); } else if (rem == 1) { CPW(1); } else { CPW(0); }
        }
        __syncthreads();
        if (c + 3 < 12) OSTAGE((c + 3) & 3, c + 3);   // buf read at c-1: safe
        uint32_t base = sb + (c & 3) * OSTB;
        uint32_t aA = base + offA, aB = base + OTC + offB;
#pragma unroll
        for (int kk = 0; kk < 4; kk++) {
            const uint32_t koff = kk * 32;
            uint32_t af[4];
            ldsm_x4(af, aA + koff);
#pragma unroll
            for (int nq = 0; nq < 2; nq++) {
                uint32_t bq[4];
                ldsm_x4(bq, aB + nq * 16 * AST * 2 + koff);
                mma_f16(acc[nq * 2 + 0], af, bq[0], bq[2]);
                mma_f16(acc[nq * 2 + 1], af, bq[1], bq[3]);
            }
        }
    }

#pragma unroll
    for (int nf = 0; nf < 4; nf++) {
        int row = m0 + wm + (lane >> 2);
        int col = n0 + wn + nf * 8 + (lane & 3) * 2;
        float b0 = bias[col], b1 = bias[col + 1];
        *(float2*)(Cf + (size_t)row * 768 + col) =
            make_float2(acc[nf][0] + b0, acc[nf][1] + b1);
        *(float2*)(Cf + (size_t)(row + 8) * 768 + col) =
            make_float2(acc[nf][2] + b0, acc[nf][3] + b1);
    }
}

// ===========================================================================
// Launch
// ===========================================================================
extern "C" void kernel_launch(void* const* d_in, const int* in_sizes, int n_in,
                              void* d_out, int out_size)
{
    const float* query = (const float*)d_in[0];
    const float* attw  = (const float*)d_in[1];
    const float* Wq    = (const float*)d_in[2];
    const float* Wk    = (const float*)d_in[3];
    const float* Wv    = (const float*)d_in[4];
    const float* Wo    = (const float*)d_in[5];
    const float* bo    = (const float*)d_in[6];
    float* out = (float*)d_out;

    __half *qf16, *wf16, *qk16, *vfp, *att16;
    cudaGetSymbolAddress((void**)&qf16, g_qf16);
    cudaGetSymbolAddress((void**)&wf16, g_wf16);
    cudaGetSymbolAddress((void**)&qk16, g_qk16);
    cudaGetSymbolAddress((void**)&vfp, g_vf);
    cudaGetSymbolAddress((void**)&att16, g_att16);

    const int proj_smem = 3 * FSTB;                // 110592 (2 CTAs/SM)
    cudaFuncSetAttribute(proj_qkv, cudaFuncAttributeMaxDynamicSharedMemorySize, proj_smem);
    const int attn_smem = 4 * STB;                 // 110592 (2 CTAs/SM)
    cudaFuncSetAttribute(attn_mma, cudaFuncAttributeMaxDynamicSharedMemorySize, attn_smem);
    const int out_smem = 4 * OSTB;                 // 73728 (2 CTAs/SM)
    cudaFuncSetAttribute(gemm_out, cudaFuncAttributeMaxDynamicSharedMemorySize, out_smem);

    // 1) All conversions (fp16) in one launch
    conv_all<<<5376, 256>>>((const float4*)query,
                            (const float4*)Wq, (const float4*)Wk,
                            (const float4*)Wv, (const float4*)Wo,
                            (uint2*)qf16, (uint2*)wf16);

    // 2) Q, K, V projections: single fp16 GEMM, z selects weight + output
    proj_qkv<<<dim3(6, 32, 3), 256, proj_smem>>>(qf16, wf16, qk16, vfp);

    // 3) Fused biased attention (4-stage pipeline) -> att fp16
    attn_mma<<<dim3(8, 12, 4), 256, attn_smem>>>(qk16, vfp, attw, att16);

    // 4) Output projection (fp16, 64x64 tiles, 4-stage) -> fp32 + bias
    gemm_out<<<dim3(12, 64), 256, out_smem>>>(att16, wf16 + 3 * (size_t)WELE, bo, out);
}

// round 17
// speedup vs baseline: 1.0449x; 1.0449x over previous
#include <cuda_runtime.h>
#include <cuda_fp16.h>
#include <math.h>
#include <cstdint>

#define TOTE (4096 * 768)
#define WELE (768 * 768)
#define AST 72     // fp16 smem row stride for 64-wide tiles (144B)
#define WSTW 36    // W fp32 smem row stride (144B)

// Scratch (allocation-free rule: __device__ globals)
__device__ __half g_qf16[TOTE];        // query fp16
__device__ __half g_wf16[4 * WELE];    // Wq|Wk|Wv|Wo fp16
__device__ __half g_qk16[2 * TOTE];    // Q|K fp16
__device__ __half g_vf[TOTE];          // V fp16
__device__ __half g_att16[TOTE];       // attention output fp16

// ===========================================================================
// Base-sm_103-safe helpers (no tcgen05: ptxas virtual target is compute_103)
// ===========================================================================
__device__ __forceinline__ uint32_t smem_u32(const void* p) {
    uint32_t a;
    asm("{ .reg .u64 t; cvta.to.shared.u64 t, %1; cvt.u32.u64 %0, t; }" : "=r"(a) : "l"(p));
    return a;
}
__device__ __forceinline__ void ldsm_x4(uint32_t* r, uint32_t addr) {
    asm volatile("ldmatrix.sync.aligned.m8n8.x4.shared.b16 {%0,%1,%2,%3}, [%4];"
                 : "=r"(r[0]), "=r"(r[1]), "=r"(r[2]), "=r"(r[3]) : "r"(addr));
}
__device__ __forceinline__ void ldsm_x4_t(uint32_t* r, uint32_t addr) {
    asm volatile("ldmatrix.sync.aligned.m8n8.x4.trans.shared.b16 {%0,%1,%2,%3}, [%4];"
                 : "=r"(r[0]), "=r"(r[1]), "=r"(r[2]), "=r"(r[3]) : "r"(addr));
}
__device__ __forceinline__ void mma_f16(float* d, const uint32_t* a, uint32_t b0, uint32_t b1) {
    asm volatile(
        "mma.sync.aligned.m16n8k16.row.col.f32.f16.f16.f32 "
        "{%0,%1,%2,%3}, {%4,%5,%6,%7}, {%8,%9}, {%0,%1,%2,%3};"
        : "+f"(d[0]), "+f"(d[1]), "+f"(d[2]), "+f"(d[3])
        : "r"(a[0]), "r"(a[1]), "r"(a[2]), "r"(a[3]), "r"(b0), "r"(b1));
}
__device__ __forceinline__ uint32_t pack_f16x2(float lo, float hi) {
    uint32_t d;
    asm("cvt.rn.f16x2.f32 %0, %1, %2;" : "=r"(d) : "f"(hi), "f"(lo));
    return d;
}
__device__ __forceinline__ void cpa16(uint32_t dst, const void* src) {
    asm volatile("cp.async.cg.shared.global [%0], [%1], 16;" :: "r"(dst), "l"(src) : "memory");
}
#define CPW(n) asm volatile("cp.async.wait_group " #n ";" ::: "memory")

// ===========================================================================
// Fused conversion: query + all four weights -> fp16, one launch.
// ===========================================================================
__global__ __launch_bounds__(256) void conv_all(
    const float4* __restrict__ q,
    const float4* __restrict__ Wq, const float4* __restrict__ Wk,
    const float4* __restrict__ Wv, const float4* __restrict__ Wo,
    uint2* __restrict__ qf16, uint2* __restrict__ wf16)
{
    const int bid = blockIdx.x;
    const int tid = threadIdx.x;
    if (bid < 3072) {
        int i = bid * 256 + tid;
        float4 v = q[i];
        __half f[4] = {__float2half_rn(v.x), __float2half_rn(v.y),
                       __float2half_rn(v.z), __float2half_rn(v.w)};
        qf16[i] = *(uint2*)f;
    } else {
        int r = bid - 3072;
        int zz = r / 576;
        int i = (r % 576) * 256 + tid;
        const float4* src = (zz == 0) ? Wq : (zz == 1) ? Wk : (zz == 2) ? Wv : Wo;
        float4 v = src[i];
        __half f[4] = {__float2half_rn(v.x), __float2half_rn(v.y),
                       __float2half_rn(v.z), __float2half_rn(v.w)};
        wf16[(size_t)zz * (WELE / 4) + i] = *(uint2*)f;
    }
}

// ===========================================================================
// Q/K/V projections: single-pass fp16 NT GEMM, one launch (z selects weight
// + output). Block tile 128x128, K-chunk 64, 3-stage cp.async, 2 CTAs/SM.
// ===========================================================================
#define FTA (128 * AST * 2)          // bytes per array per stage (18432)
#define FSTB (2 * FTA)               // stage stride (36864)

__global__ __launch_bounds__(256, 2) void proj_qkv(
    const __half* __restrict__ Af, const __half* __restrict__ Wf,
    __half* __restrict__ qk, __half* __restrict__ vf)
{
    extern __shared__ __align__(16) __half smh[];
    const uint32_t sb = smem_u32(smh);

    const int tid = threadIdx.x, wid = tid >> 5, lane = tid & 31;
    const int wm = (wid >> 1) * 32, wn = (wid & 1) * 64;
    const int m0 = blockIdx.y * 128, n0 = blockIdx.x * 128;
    const int z = blockIdx.z;

    const __half* gA = Af + (size_t)m0 * 768;
    const __half* gB = Wf + (size_t)z * WELE + (size_t)n0 * 768;
    __half* dst = (z == 2) ? vf : qk + (size_t)z * TOTE;

    float acc[2][8][4];
#pragma unroll
    for (int i = 0; i < 2; i++)
#pragma unroll
        for (int j = 0; j < 8; j++)
#pragma unroll
            for (int k = 0; k < 4; k++) acc[i][j][k] = 0.f;

#define PSTAGE(buf, c_)                                                        \
    {                                                                          \
        uint32_t base_ = sb + (buf) * FSTB;                                    \
        const int k0_ = (c_) * 64;                                             \
        _Pragma("unroll")                                                      \
        for (int it = 0; it < 4; it++) {                                       \
            int idx = it * 256 + tid;                                          \
            int row = idx >> 3, cc = idx & 7;                                  \
            uint32_t off = (uint32_t)(row * AST + cc * 8) * 2;                 \
            size_t go = (size_t)row * 768 + k0_ + cc * 8;                      \
            cpa16(base_ + off,       gA + go);                                 \
            cpa16(base_ + FTA + off, gB + go);                                 \
        }                                                                      \
        asm volatile("cp.async.commit_group;" ::: "memory");                   \
    }

    PSTAGE(0, 0); PSTAGE(1, 1);

    const int lrow = lane & 15, lcol8 = (lane >> 4) * 8;
    const uint32_t offA = (uint32_t)((wm + lrow) * AST + lcol8) * 2;
    const uint32_t offB = (uint32_t)((wn + lrow) * AST + lcol8) * 2;

    for (int c = 0; c < 12; c++) {
        if (c + 2 < 12) { CPW(1); } else { CPW(0); }
        __syncthreads();
        if (c + 2 < 12) PSTAGE((c + 2) % 3, c + 2);
        uint32_t base = sb + (c % 3) * FSTB;
        uint32_t aA = base + offA, aB = base + FTA + offB;
#pragma unroll
        for (int kk = 0; kk < 4; kk++) {
            const uint32_t koff = kk * 32;
            uint32_t af[2][4];
#pragma unroll
            for (int mf = 0; mf < 2; mf++)
                ldsm_x4(af[mf], aA + mf * 16 * AST * 2 + koff);
#pragma unroll
            for (int nq = 0; nq < 4; nq++) {
                uint32_t bq[4];
                ldsm_x4(bq, aB + nq * 16 * AST * 2 + koff);
#pragma unroll
                for (int mf = 0; mf < 2; mf++) {
                    mma_f16(acc[mf][nq * 2 + 0], af[mf], bq[0], bq[2]);
                    mma_f16(acc[mf][nq * 2 + 1], af[mf], bq[1], bq[3]);
                }
            }
        }
    }

#pragma unroll
    for (int mf = 0; mf < 2; mf++) {
#pragma unroll
        for (int nf = 0; nf < 8; nf++) {
            int row = m0 + wm + mf * 16 + (lane >> 2);
            int col = n0 + wn + nf * 8 + (lane & 3) * 2;
            __half2 h0 = __floats2half2_rn(acc[mf][nf][0], acc[mf][nf][1]);
            __half2 h1 = __floats2half2_rn(acc[mf][nf][2], acc[mf][nf][3]);
            *(uint32_t*)(dst + (size_t)row * 768 + col) = *(uint32_t*)&h0;
            *(uint32_t*)(dst + (size_t)(row + 8) * 768 + col) = *(uint32_t*)&h1;
        }
    }
}

// ===========================================================================
// HMMA fused biased flash attention: fp16 QK + fp16 PV, no-max softmax.
// v6: 64 queries / 128 threads / 4 warps per CTA -> 768 CTAs (2.6 waves of
// 4-CTA/SM slots: fine-grained balance). Per-warp structure unchanged
// (16 query rows each). Key tile 32, 3-stage cp.async, 4 CTAs/SM.
// ===========================================================================
#define KT 32
#define KVB (KT * AST * 2)            // 4608 B per K/V array per stage
#define WB  (64 * WSTW * 4)           // 9216 B W tile (64 q rows) per stage
#define STB (2 * KVB + WB)            // stage stride 18432 B

__global__ __launch_bounds__(128, 4) void attn_mma(
    const __half* __restrict__ qk16, const __half* __restrict__ vf,
    const float* __restrict__ W, __half* __restrict__ att16)
{
    extern __shared__ __align__(16) char smn[];
    const uint32_t sb = smem_u32(smn);

    const int tid = threadIdx.x, wp = tid >> 5, lane = tid & 31;
    const int n0 = blockIdx.x * 64, h = blockIdx.y, b = blockIdx.z;

    const __half* qg = qk16 + ((size_t)(b * 1024 + n0)) * 768 + h * 64;
    const __half* kg = qk16 + (size_t)TOTE + (size_t)b * 1024 * 768 + h * 64;
    const __half* vg = vf + (size_t)b * 1024 * 768 + h * 64;
    const float* wg = W + ((size_t)(b * 12 + h) * 1024 + n0) * 1024;

    // --- Stage Q (64x64 fp16) through smem (pre-pipeline), frags to regs ---
    {
        __half* tQ = (__half*)smn;
#pragma unroll
        for (int it = 0; it < 4; it++) {
            int idx = it * 128 + tid;
            int row = idx >> 3, cc = idx & 7;
            *(uint4*)(tQ + row * AST + cc * 8) = *(const uint4*)(qg + (size_t)row * 768 + cc * 8);
        }
    }
    __syncthreads();
    uint32_t qf[4][4];
    {
        uint32_t off = (uint32_t)((wp * 16 + (lane & 15)) * AST + (lane >> 4) * 8) * 2;
#pragma unroll
        for (int ks = 0; ks < 4; ks++)
            ldsm_x4(qf[ks], sb + off + ks * 32);
    }
    __syncthreads();

    float oacc[8][4];
#pragma unroll
    for (int d = 0; d < 8; d++)
#pragma unroll
        for (int j = 0; j < 4; j++) oacc[d][j] = 0.f;
    float l0r = 0.f, l1r = 0.f;

#define ASTAGE(buf, t_)                                                        \
    {                                                                          \
        uint32_t base_ = sb + (buf) * STB;                                     \
        const int s0_ = (t_) * KT;                                             \
        _Pragma("unroll")                                                      \
        for (int it = 0; it < 2; it++) {                                       \
            int idx = it * 128 + tid;                                          \
            int row = idx >> 3, cc = idx & 7;                                  \
            uint32_t doff = (uint32_t)(row * AST + cc * 8) * 2;                \
            size_t go = (size_t)(s0_ + row) * 768 + cc * 8;                    \
            cpa16(base_ + doff,       kg + go);                                \
            cpa16(base_ + KVB + doff, vg + go);                                \
        }                                                                      \
        _Pragma("unroll")                                                      \
        for (int it = 0; it < 4; it++) {                                       \
            int idx = it * 128 + tid;                                          \
            int row = idx >> 3, cc = idx & 7;                                  \
            cpa16(base_ + 2 * KVB + (uint32_t)(row * WSTW + cc * 4) * 4,       \
                  wg + (size_t)row * 1024 + s0_ + cc * 4);                     \
        }                                                                      \
        asm volatile("cp.async.commit_group;" ::: "memory");                   \
    }

    ASTAGE(0, 0); ASTAGE(1, 1);

    const uint32_t foff = (uint32_t)(((lane & 15) * AST) + (lane >> 4) * 8) * 2;
    const int c0 = (lane & 3) * 2;
    const uint32_t woff = (uint32_t)((wp * 16 + (lane >> 2)) * WSTW + c0) * 4;

    for (int t = 0; t < 32; t++) {
        if (t + 2 < 32) { CPW(1); } else { CPW(0); }
        __syncthreads();
        if (t + 2 < 32) ASTAGE((t + 2) % 3, t + 2);   // stage read at t-1: safe
        uint32_t base = sb + (t % 3) * STB;
        uint32_t kbb = base + foff;
        uint32_t vbb = base + KVB + foff;
        uint32_t wb0 = base + 2 * KVB + woff;

        // ---- S = Q K^T (fp16), 32 keys ----
        float sc[4][4];
#pragma unroll
        for (int nf = 0; nf < 4; nf++)
#pragma unroll
            for (int j = 0; j < 4; j++) sc[nf][j] = 0.f;
#pragma unroll
        for (int nf2 = 0; nf2 < 2; nf2++) {
#pragma unroll
            for (int ks = 0; ks < 4; ks++) {
                uint32_t fh[4];
                ldsm_x4(fh, kbb + (uint32_t)(nf2 * 16 * AST + ks * 16) * 2);
                mma_f16(sc[2 * nf2],     qf[ks], fh[0], fh[2]);
                mma_f16(sc[2 * nf2 + 1], qf[ks], fh[1], fh[3]);
            }
        }

        // ---- p = exp(W + scale*S) directly (bounded logits, no max) ----
        float rs0 = 0.f, rs1 = 0.f;
#pragma unroll
        for (int nf = 0; nf < 4; nf++) {
            float2 w0, w1;
            asm volatile("ld.shared.v2.f32 {%0,%1}, [%2];"
                         : "=f"(w0.x), "=f"(w0.y) : "r"(wb0 + nf * 32));
            asm volatile("ld.shared.v2.f32 {%0,%1}, [%2];"
                         : "=f"(w1.x), "=f"(w1.y) : "r"(wb0 + 8 * WSTW * 4 + nf * 32));
            sc[nf][0] = __expf(fmaf(sc[nf][0], 0.125f, w0.x));
            sc[nf][1] = __expf(fmaf(sc[nf][1], 0.125f, w0.y));
            sc[nf][2] = __expf(fmaf(sc[nf][2], 0.125f, w1.x));
            sc[nf][3] = __expf(fmaf(sc[nf][3], 0.125f, w1.y));
            rs0 += sc[nf][0] + sc[nf][1];
            rs1 += sc[nf][2] + sc[nf][3];
        }
        l0r += rs0;
        l1r += rs1;

        // ---- out += P V (fp16, P from registers) ----
#pragma unroll
        for (int kc = 0; kc < 2; kc++) {
            uint32_t pa[4];
            pa[0] = pack_f16x2(sc[2 * kc][0], sc[2 * kc][1]);
            pa[1] = pack_f16x2(sc[2 * kc][2], sc[2 * kc][3]);
            pa[2] = pack_f16x2(sc[2 * kc + 1][0], sc[2 * kc + 1][1]);
            pa[3] = pack_f16x2(sc[2 * kc + 1][2], sc[2 * kc + 1][3]);
#pragma unroll
            for (int dp = 0; dp < 4; dp++) {
                uint32_t vf4[4];
                ldsm_x4_t(vf4, vbb + (uint32_t)(kc * 16 * AST + dp * 16) * 2);
                mma_f16(oacc[2 * dp],     pa, vf4[0], vf4[1]);
                mma_f16(oacc[2 * dp + 1], pa, vf4[2], vf4[3]);
            }
        }
    }

    // ---- normalize + write fp16 (att layout [4096, 768]) ----
    l0r += __shfl_xor_sync(0xffffffffu, l0r, 1);
    l0r += __shfl_xor_sync(0xffffffffu, l0r, 2);
    l1r += __shfl_xor_sync(0xffffffffu, l1r, 1);
    l1r += __shfl_xor_sync(0xffffffffu, l1r, 2);
    float i0 = 1.f / l0r, i1 = 1.f / l1r;
    int row = b * 1024 + n0 + wp * 16 + (lane >> 2);
    int colb = h * 64 + c0;
#pragma unroll
    for (int d = 0; d < 8; d++) {
        __half2 h0 = __floats2half2_rn(oacc[d][0] * i0, oacc[d][1] * i0);
        __half2 h1 = __floats2half2_rn(oacc[d][2] * i1, oacc[d][3] * i1);
        *(uint32_t*)(att16 + (size_t)row * 768 + colb + d * 8) = *(uint32_t*)&h0;
        *(uint32_t*)(att16 + (size_t)(row + 8) * 768 + colb + d * 8) = *(uint32_t*)&h1;
    }
}

// ===========================================================================
// Output projection: single-pass fp16 NT GEMM, fp32 + bias epilogue.
// Block tile 64x128 (R15 config: 384 CTAs), K-chunk 64, 3-stage, 2 CTAs/SM.
// 8 warps = 2m x 4n, warp tile 32x32.
// ===========================================================================
#define OTA (64 * AST * 2)           // A array bytes/stage (9216)
#define OTB (128 * AST * 2)          // B array bytes/stage (18432)
#define OSTB (OTA + OTB)             // stage stride (27648)

__global__ __launch_bounds__(256, 2) void gemm_out(
    const __half* __restrict__ Af, const __half* __restrict__ Bf,
    const float* __restrict__ bias, float* __restrict__ Cf)
{
    extern __shared__ __align__(16) __half smh[];
    const uint32_t sb = smem_u32(smh);

    const int tid = threadIdx.x, wid = tid >> 5, lane = tid & 31;
    const int wm = (wid >> 2) * 32, wn = (wid & 3) * 32;
    const int m0 = blockIdx.y * 64, n0 = blockIdx.x * 128;

    const __half* gA = Af + (size_t)m0 * 768;
    const __half* gB = Bf + (size_t)n0 * 768;

    float acc[2][4][4];
#pragma unroll
    for (int i = 0; i < 2; i++)
#pragma unroll
        for (int j = 0; j < 4; j++)
#pragma unroll
            for (int k = 0; k < 4; k++) acc[i][j][k] = 0.f;

#define OSTAGE(buf, c_)                                                        \
    {                                                                          \
        uint32_t base_ = sb + (buf) * OSTB;                                    \
        const int k0_ = (c_) * 64;                                             \
        _Pragma("unroll")                                                      \
        for (int it = 0; it < 2; it++) {                                       \
            int idx = it * 256 + tid;                                          \
            int row = idx >> 3, cc = idx & 7;                                  \
            uint32_t off = (uint32_t)(row * AST + cc * 8) * 2;                 \
            cpa16(base_ + off, gA + (size_t)row * 768 + k0_ + cc * 8);         \
        }                                                                      \
        _Pragma("unroll")                                                      \
        for (int it = 0; it < 4; it++) {                                       \
            int idx = it * 256 + tid;                                          \
            int row = idx >> 3, cc = idx & 7;                                  \
            uint32_t off = (uint32_t)(row * AST + cc * 8) * 2;                 \
            cpa16(base_ + OTA + off, gB + (size_t)row * 768 + k0_ + cc * 8);   \
        }                                                                      \
        asm volatile("cp.async.commit_group;" ::: "memory");                   \
    }

    OSTAGE(0, 0); OSTAGE(1, 1);

    const int lrow = lane & 15, lcol8 = (lane >> 4) * 8;
    const uint32_t offA = (uint32_t)((wm + lrow) * AST + lcol8) * 2;
    const uint32_t offB = (uint32_t)((wn + lrow) * AST + lcol8) * 2;

    for (int c = 0; c < 12; c++) {
        if (c + 2 < 12) { CPW(1); } else { CPW(0); }
        __syncthreads();
        if (c + 2 < 12) OSTAGE((c + 2) % 3, c + 2);
        uint32_t base = sb + (c % 3) * OSTB;
        uint32_t aA = base + offA, aB = base + OTA + offB;
#pragma unroll
        for (int kk = 0; kk < 4; kk++) {
            const uint32_t koff = kk * 32;
            uint32_t af[2][4];
#pragma unroll
            for (int mf = 0; mf < 2; mf++)
                ldsm_x4(af[mf], aA + mf * 16 * AST * 2 + koff);
#pragma unroll
            for (int nq = 0; nq < 2; nq++) {
                uint32_t bq[4];
                ldsm_x4(bq, aB + nq * 16 * AST * 2 + koff);
#pragma unroll
                for (int mf = 0; mf < 2; mf++) {
                    mma_f16(acc[mf][nq * 2 + 0], af[mf], bq[0], bq[2]);
                    mma_f16(acc[mf][nq * 2 + 1], af[mf], bq[1], bq[3]);
                }
            }
        }
    }

#pragma unroll
    for (int mf = 0; mf < 2; mf++) {
#pragma unroll
        for (int nf = 0; nf < 4; nf++) {
            int row = m0 + wm + mf * 16 + (lane >> 2);
            int col = n0 + wn + nf * 8 + (lane & 3) * 2;
            float b0 = bias[col], b1 = bias[col + 1];
            *(float2*)(Cf + (size_t)row * 768 + col) =
                make_float2(acc[mf][nf][0] + b0, acc[mf][nf][1] + b1);
            *(float2*)(Cf + (size_t)(row + 8) * 768 + col) =
                make_float2(acc[mf][nf][2] + b0, acc[mf][nf][3] + b1);
        }
    }
}

// ===========================================================================
// Launch
// ===========================================================================
extern "C" void kernel_launch(void* const* d_in, const int* in_sizes, int n_in,
                              void* d_out, int out_size)
{
    const float* query = (const float*)d_in[0];
    const float* attw  = (const float*)d_in[1];
    const float* Wq    = (const float*)d_in[2];
    const float* Wk    = (const float*)d_in[3];
    const float* Wv    = (const float*)d_in[4];
    const float* Wo    = (const float*)d_in[5];
    const float* bo    = (const float*)d_in[6];
    float* out = (float*)d_out;

    __half *qf16, *wf16, *qk16, *vfp, *att16;
    cudaGetSymbolAddress((void**)&qf16, g_qf16);
    cudaGetSymbolAddress((void**)&wf16, g_wf16);
    cudaGetSymbolAddress((void**)&qk16, g_qk16);
    cudaGetSymbolAddress((void**)&vfp, g_vf);
    cudaGetSymbolAddress((void**)&att16, g_att16);

    const int proj_smem = 3 * FSTB;                // 110592 (2 CTAs/SM)
    cudaFuncSetAttribute(proj_qkv, cudaFuncAttributeMaxDynamicSharedMemorySize, proj_smem);
    const int attn_smem = 3 * STB;                 // 55296 (4 CTAs/SM)
    cudaFuncSetAttribute(attn_mma, cudaFuncAttributeMaxDynamicSharedMemorySize, attn_smem);
    const int out_smem = 3 * OSTB;                 // 82944 (2 CTAs/SM)
    cudaFuncSetAttribute(gemm_out, cudaFuncAttributeMaxDynamicSharedMemorySize, out_smem);

    // 1) All conversions (fp16) in one launch
    conv_all<<<5376, 256>>>((const float4*)query,
                            (const float4*)Wq, (const float4*)Wk,
                            (const float4*)Wv, (const float4*)Wo,
                            (uint2*)qf16, (uint2*)wf16);

    // 2) Q, K, V projections: single fp16 GEMM, z selects weight + output
    proj_qkv<<<dim3(6, 32, 3), 256, proj_smem>>>(qf16, wf16, qk16, vfp);

    // 3) Fused biased attention (64-q CTAs, 4 CTAs/SM) -> att fp16
    attn_mma<<<dim3(16, 12, 4), 128, attn_smem>>>(qk16, vfp, attw, att16);

    // 4) Output projection (fp16, 64x128 tiles) -> fp32 + bias
    gemm_out<<<dim3(6, 64), 256, out_smem>>>(att16, wf16 + 3 * (size_t)WELE, bo, out);
}